// round 6
// baseline (speedup 1.0000x reference)
#include <cuda_runtime.h>
#include <cuda_bf16.h>
#include <cstdint>

#define EPSF 1e-8f
static constexpr int B_  = 8;
static constexpr int N_  = 256;
static constexpr int NF_ = 2048;

__device__ __nv_bfloat16 g_K[B_ * N_ * N_];   // bf16 K, L2-resident
__device__ float g_KTu[B_ * N_];              // accumulated K^T u1 (reset by elected CTA)
__device__ float g_p  [B_ * N_];
__device__ float g_u1 [B_ * N_];
__device__ float g_u2 [B_ * N_];
__device__ float g_cp [B_ * N_];              // coupling accumulator per row
__device__ float g_S  [B_];
__device__ int   g_conv[B_];
__device__ int   g_cnt [B_];

// ---------------------------------------------------------------------------
// helpers
// ---------------------------------------------------------------------------
__device__ __forceinline__ void unpack8(uint4 kr, float* f)
{
    float2 f0 = __bfloat1622float2(*reinterpret_cast<__nv_bfloat162*>(&kr.x));
    float2 f1 = __bfloat1622float2(*reinterpret_cast<__nv_bfloat162*>(&kr.y));
    float2 f2 = __bfloat1622float2(*reinterpret_cast<__nv_bfloat162*>(&kr.z));
    float2 f3 = __bfloat1622float2(*reinterpret_cast<__nv_bfloat162*>(&kr.w));
    f[0] = f0.x; f[1] = f0.y; f[2] = f1.x; f[3] = f1.y;
    f[4] = f2.x; f[5] = f2.y; f[6] = f3.x; f[7] = f3.y;
}

__device__ __forceinline__ float dot8(uint4 kr, const float* vj)
{
    float kf[8];
    unpack8(kr, kf);
    float acc = 0.f;
#pragma unroll
    for (int x = 0; x < 8; ++x) acc = fmaf(kf[x], vj[x], acc);
    return acc;
}

// 256-thread broadcast sum (fallback path)
__device__ __forceinline__ float blk_sum256(float val, float* red)
{
#pragma unroll
    for (int o = 16; o; o >>= 1) val += __shfl_xor_sync(0xffffffffu, val, o);
    if ((threadIdx.x & 31) == 0) red[threadIdx.x >> 5] = val;
    __syncthreads();
    if (threadIdx.x < 32) {
        float s = (threadIdx.x < 8) ? red[threadIdx.x] : 0.f;
#pragma unroll
        for (int o = 4; o; o >>= 1) s += __shfl_xor_sync(0xffffffffu, s, o);
        if (threadIdx.x == 0) red[8] = s;
    }
    __syncthreads();
    float r = red[8];
    __syncthreads();
    return r;
}

// ---------------------------------------------------------------------------
// Kernel 1: pooling -> K (bf16); two combined reduction rounds:
//   round1: (sum w, max gamma)   round2: (sum K, sum exp(gamma-m))
// then u1[I] = p[I]/(rsK/256+EPS) and REDG of K^T u1 into g_KTu.
// Grid (256,8), 256 threads, <=32 regs (8 CTAs/SM).
// ---------------------------------------------------------------------------
__global__ void __launch_bounds__(256, 8) pool_build_k(
    const float* __restrict__ A, const float* __restrict__ gamma_g)
{
    const int I = blockIdx.x, b = blockIdx.y;
    const int t = threadIdx.x;
    const int wd = t >> 5, lane = t & 31;
    const float* base = A + ((size_t)b * NF_ + (size_t)I * 8) * NF_;

    float gmine = gamma_g[b * N_ + t];
    float gI    = __ldg(&gamma_g[b * N_ + I]);

    float4 a0 = make_float4(0.f, 0.f, 0.f, 0.f);
    float4 a1 = make_float4(0.f, 0.f, 0.f, 0.f);
#pragma unroll
    for (int r = 0; r < 8; ++r) {
        const float4* row = reinterpret_cast<const float4*>(base + (size_t)r * NF_);
        float4 f0 = __ldcs(row + t);
        float4 f1 = __ldcs(row + t + 256);
        a0.x += f0.x; a0.y += f0.y; a0.z += f0.z; a0.w += f0.w;
        a1.x += f1.x; a1.y += f1.y; a1.z += f1.z; a1.w += f1.w;
    }
    float s0 = (a0.x + a0.y) + (a0.z + a0.w);
    float s1 = (a1.x + a1.y) + (a1.z + a1.w);
    s0 += __shfl_xor_sync(0xffffffffu, s0, 1);
    s1 += __shfl_xor_sync(0xffffffffu, s1, 1);

    __shared__ float srow[256];
    __shared__ float rA[9], rB[9], rC[9], rD[9];
    if ((t & 1) == 0) {
        srow[(t >> 1)]       = s0 * (1.0f / 64.0f);
        srow[128 + (t >> 1)] = s1 * (1.0f / 64.0f);
    }
    __syncthreads();

    float w = fmaxf(srow[t], 0.0f);                 // relu(A_lat[I, t])

    // ---- round 1: (sum w, max gamma) ----
    {
        float sv = w, mv = gmine;
#pragma unroll
        for (int o = 16; o; o >>= 1) {
            sv += __shfl_xor_sync(0xffffffffu, sv, o);
            mv  = fmaxf(mv, __shfl_xor_sync(0xffffffffu, mv, o));
        }
        if (lane == 0) { rA[wd] = sv; rB[wd] = mv; }
    }
    __syncthreads();
    if (t < 32) {
        float s = (t < 8) ? rA[t] : 0.f;
        float m = (t < 8) ? rB[t] : -3.4e38f;
#pragma unroll
        for (int o = 4; o; o >>= 1) {
            s += __shfl_xor_sync(0xffffffffu, s, o);
            m  = fmaxf(m, __shfl_xor_sync(0xffffffffu, m, o));
        }
        if (t == 0) { rA[8] = s; rB[8] = m; }
    }
    __syncthreads();
    const float rowsum = rA[8], gmax = rB[8];

    float W = (rowsum > EPSF) ? (w / (rowsum + EPSF)) : (1.0f / N_);
    float x  = W + EPSF;
    float x2 = x * x, x4 = x2 * x2, x8 = x4 * x4;
    __nv_bfloat16 kb = __float2bfloat16(x8 * x2);   // K = x^10 (bf16)
    g_K[((size_t)b * N_ + I) * N_ + t] = kb;

    float kf = __bfloat162float(kb);
    float e  = expf(gmine - gmax);

    // ---- round 2: (sum K, sum exp) ----
    {
        float sv = kf, ev = e;
#pragma unroll
        for (int o = 16; o; o >>= 1) {
            sv += __shfl_xor_sync(0xffffffffu, sv, o);
            ev += __shfl_xor_sync(0xffffffffu, ev, o);
        }
        if (lane == 0) { rC[wd] = sv; rD[wd] = ev; }
    }
    __syncthreads();
    if (t < 32) {
        float s = (t < 8) ? rC[t] : 0.f;
        float v = (t < 8) ? rD[t] : 0.f;
#pragma unroll
        for (int o = 4; o; o >>= 1) {
            s += __shfl_xor_sync(0xffffffffu, s, o);
            v += __shfl_xor_sync(0xffffffffu, v, o);
        }
        if (t == 0) { rC[8] = s; rD[8] = v; }
    }
    __syncthreads();
    const float rsK = rC[8], esum = rD[8];

    float pI  = expf(gI - gmax) / esum;
    float u1I = pI / (rsK * (1.0f / N_) + EPSF);    // Kv0 = rsK/256

    atomicAdd(&g_KTu[b * N_ + t], kf * u1I);        // K^T u1, row I's contribution
    if (t == 0) {
        g_p [b * N_ + I] = pI;
        g_u1[b * N_ + I] = u1I;
    }
}

// ---------------------------------------------------------------------------
// Kernel 2: single post-pool K pass + in-kernel finalization via election.
// Grid (16,8) = 128 CTAs, 256 thr. Each chunk: v1, Kv1, u2, conv-check,
// coupling; atomicAdd S; 16th arriver per batch writes the batch's output
// (or runs the faithful full-Sinkhorn fallback if not converged).
// ---------------------------------------------------------------------------
__global__ void __launch_bounds__(256) epi_main(
    const float* __restrict__ theta_g, const float* __restrict__ gamma_g,
    const float* __restrict__ omega_g, const float* __restrict__ alpha_g,
    const float* __restrict__ logk_g,  float* __restrict__ out)
{
    __shared__ float v1sh[256];     // fallback reuses as v
    __shared__ float tsh[256];
    __shared__ float p_s[256];      // fallback only
    __shared__ float u_s[256];      // fallback only
    __shared__ float kv_s[256];     // fallback only
    __shared__ float red[10];
    __shared__ int   rank;

    const int b     = blockIdx.y;
    const int chunk = blockIdx.x;
    const int t     = threadIdx.x;
    const int row   = t >> 4;
    const int sub   = t & 15;
    const int i     = chunk * 16 + row;
    const int gi    = b * N_ + i;
    const int j0    = sub * 16;

    float kt = g_KTu[b * N_ + t];
    v1sh[t]  = (1.0f / N_) / (kt + EPSF);
    tsh[t]   = theta_g[b * N_ + t];
    __syncthreads();

    // ---- chunk work: Kv1 + coupling for 16 rows ----
    {
        uint4 k0 = reinterpret_cast<const uint4*>(g_K + (size_t)gi * N_ + j0)[0];
        uint4 k1 = reinterpret_cast<const uint4*>(g_K + (size_t)gi * N_ + j0)[1];
        float kf[16];
        unpack8(k0, kf);
        unpack8(k1, kf + 8);

        const float4* a4 = reinterpret_cast<const float4*>(alpha_g + (size_t)i * N_ + j0);
        float4 al0 = __ldg(a4 + 0);
        float4 al1 = __ldg(a4 + 1);
        float4 al2 = __ldg(a4 + 2);
        float4 al3 = __ldg(a4 + 3);
        float al[16] = {al0.x, al0.y, al0.z, al0.w, al1.x, al1.y, al1.z, al1.w,
                        al2.x, al2.y, al2.z, al2.w, al3.x, al3.y, al3.z, al3.w};

        const float ti = tsh[i];
        float kv = 0.f, cp = 0.f;
#pragma unroll
        for (int x = 0; x < 16; ++x) {
            float kvj = kf[x] * v1sh[j0 + x];
            kv += kvj;
            float d = tsh[j0 + x] - ti - al[x];
            cp = fmaf(kvj, __sinf(d), cp);
        }
#pragma unroll
        for (int o = 8; o; o >>= 1) {
            kv += __shfl_xor_sync(0xffffffffu, kv, o);
            cp += __shfl_xor_sync(0xffffffffu, cp, o);
        }

        if (sub == 0) {
            float u1 = g_u1[gi];
            float u2 = g_p[gi] / (kv + EPSF);
            if (u2 != u1) g_conv[b] = 1;          // not converged after iter 2
            g_u2[gi] = u2;
            g_cp[gi] = cp;
            atomicAdd(&g_S[b], u2 * kv);
        }
    }

    // ---- election: 16th arriver finalizes this batch ----
    __threadfence();
    __syncthreads();
    if (t == 0) rank = atomicAdd(&g_cnt[b], 1);
    __syncthreads();
    if (rank != 15) return;
    __threadfence();

    const int conv = __ldcg(&g_conv[b]);

    if (conv == 0) {
        // -------- converged fast path: write the 256 outputs --------
        float S = __ldcg(&g_S[b]);
        float Sinv = 1.0f / (S + EPSF);
        float u2 = __ldcg(&g_u2[b * N_ + t]);
        float cp = __ldcg(&g_cp[b * N_ + t]);
        float ti = tsh[t];
        float kap = log1pf(expf(logk_g[t]));                 // softplus
        float td  = omega_g[t] + u2 * Sinv * cp + kap * (gamma_g[b * N_ + t] - ti);
        out[b * N_ + t] = ti + td;                           // DT=1, K_COUP=1
    } else {
        // -------- fallback: faithful 10-iter Sinkhorn from scratch --------
        const int wd = t >> 5, lane = t & 31;
        p_s[t] = __ldcg(&g_p[b * N_ + t]);
        u_s[t] = 1.0f / N_;
        v1sh[t] = 1.0f / N_;
        __syncthreads();

        for (int it = 0; it < 10; ++it) {
            // u-update: 8 warps x 32 rows, K from L2
#pragma unroll 1
            for (int k = 0; k < 32; ++k) {
                int ii = wd * 32 + k;
                uint4 kr = reinterpret_cast<const uint4*>(g_K + ((size_t)b * N_ + ii) * N_)[lane];
                float acc = dot8(kr, &v1sh[lane * 8]);
#pragma unroll
                for (int o = 16; o; o >>= 1) acc += __shfl_xor_sync(0xffffffffu, acc, o);
                if (lane == 0) u_s[ii] = p_s[ii] / (acc + EPSF);
            }
            __syncthreads();
            // v-update: thread t = column j
            float s = 0.f;
#pragma unroll 1
            for (int ii = 0; ii < N_; ++ii)
                s = fmaf(__bfloat162float(g_K[((size_t)b * N_ + ii) * N_ + t]), u_s[ii], s);
            __syncthreads();
            v1sh[t] = (1.0f / N_) / (s + EPSF);
            __syncthreads();
        }

        // final Kv, S
#pragma unroll 1
        for (int k = 0; k < 32; ++k) {
            int ii = wd * 32 + k;
            uint4 kr = reinterpret_cast<const uint4*>(g_K + ((size_t)b * N_ + ii) * N_)[lane];
            float acc = dot8(kr, &v1sh[lane * 8]);
#pragma unroll
            for (int o = 16; o; o >>= 1) acc += __shfl_xor_sync(0xffffffffu, acc, o);
            if (lane == 0) kv_s[ii] = acc;
        }
        __syncthreads();
        float S = blk_sum256(u_s[t] * kv_s[t], red);
        float Sinv = 1.0f / (S + EPSF);

        // coupling: thread t = row i
        float ti = tsh[t];
        float acc = 0.f;
#pragma unroll 1
        for (int j = 0; j < N_; ++j) {
            float kv = __bfloat162float(g_K[((size_t)b * N_ + t) * N_ + j]) * v1sh[j];
            float d  = tsh[j] - ti - alpha_g[(size_t)t * N_ + j];
            acc = fmaf(kv, __sinf(d), acc);
        }
        float kap = log1pf(expf(logk_g[t]));
        float td  = omega_g[t] + u_s[t] * Sinv * acc + kap * (gamma_g[b * N_ + t] - ti);
        out[b * N_ + t] = ti + td;
    }

    // -------- housekeeping for next graph replay --------
    g_KTu[b * N_ + t] = 0.f;
    if (t == 0) { g_S[b] = 0.f; g_conv[b] = 0; g_cnt[b] = 0; }
}

// ---------------------------------------------------------------------------
extern "C" void kernel_launch(void* const* d_in, const int* in_sizes, int n_in,
                              void* d_out, int out_size)
{
    const float* theta = (const float*)d_in[0];
    const float* gamma = (const float*)d_in[1];
    const float* A     = (const float*)d_in[2];
    const float* omega = (const float*)d_in[3];
    const float* alpha = (const float*)d_in[4];
    const float* logk  = (const float*)d_in[5];
    float* out = (float*)d_out;

    dim3 g1(256, 8);
    pool_build_k<<<g1, 256>>>(A, gamma);

    dim3 g2(16, 8);
    epi_main<<<g2, 256>>>(theta, gamma, omega, alpha, logk, out);
}

// round 7
// speedup vs baseline: 1.0580x; 1.0580x over previous
#include <cuda_runtime.h>
#include <cuda_bf16.h>
#include <cstdint>

#define EPSF 1e-8f
static constexpr int B_  = 8;
static constexpr int N_  = 256;
static constexpr int NF_ = 2048;

__device__ __nv_bfloat16 g_K[B_ * N_ * N_];   // bf16 K, L2-resident
__device__ float g_KTu[B_ * N_];              // accumulated K^T u1 (reset by elected CTA)
__device__ float g_p  [B_ * N_];
__device__ float g_u1 [B_ * N_];
__device__ float g_u2 [B_ * N_];
__device__ float g_cp [B_ * N_];              // coupling accumulator per row
__device__ float g_S  [B_];
__device__ int   g_conv[B_];
__device__ int   g_cnt [B_];

// ---------------------------------------------------------------------------
// helpers
// ---------------------------------------------------------------------------
__device__ __forceinline__ void unpack8(uint4 kr, float* f)
{
    float2 f0 = __bfloat1622float2(*reinterpret_cast<__nv_bfloat162*>(&kr.x));
    float2 f1 = __bfloat1622float2(*reinterpret_cast<__nv_bfloat162*>(&kr.y));
    float2 f2 = __bfloat1622float2(*reinterpret_cast<__nv_bfloat162*>(&kr.z));
    float2 f3 = __bfloat1622float2(*reinterpret_cast<__nv_bfloat162*>(&kr.w));
    f[0] = f0.x; f[1] = f0.y; f[2] = f1.x; f[3] = f1.y;
    f[4] = f2.x; f[5] = f2.y; f[6] = f3.x; f[7] = f3.y;
}

__device__ __forceinline__ float dot8(uint4 kr, const float* vj)
{
    float kf[8];
    unpack8(kr, kf);
    float acc = 0.f;
#pragma unroll
    for (int x = 0; x < 8; ++x) acc = fmaf(kf[x], vj[x], acc);
    return acc;
}

// 256-thread broadcast sum (fallback path)
__device__ __forceinline__ float blk_sum256(float val, float* red)
{
#pragma unroll
    for (int o = 16; o; o >>= 1) val += __shfl_xor_sync(0xffffffffu, val, o);
    if ((threadIdx.x & 31) == 0) red[threadIdx.x >> 5] = val;
    __syncthreads();
    if (threadIdx.x < 32) {
        float s = (threadIdx.x < 8) ? red[threadIdx.x] : 0.f;
#pragma unroll
        for (int o = 4; o; o >>= 1) s += __shfl_xor_sync(0xffffffffu, s, o);
        if (threadIdx.x == 0) red[8] = s;
    }
    __syncthreads();
    float r = red[8];
    __syncthreads();
    return r;
}

// ---------------------------------------------------------------------------
// Kernel 1: pooling -> K (bf16); two combined reduction rounds:
//   round1: (sum w, max gamma)   round2: (sum K, sum exp(gamma-m))
// then u1[I] = p[I]/(rsK/256+EPS) and REDG of K^T u1 into g_KTu.
// Grid (256,8), 256 threads, <=32 regs (8 CTAs/SM).
// ---------------------------------------------------------------------------
__global__ void __launch_bounds__(256, 8) pool_build_k(
    const float* __restrict__ A, const float* __restrict__ gamma_g)
{
    const int I = blockIdx.x, b = blockIdx.y;
    const int t = threadIdx.x;
    const int wd = t >> 5, lane = t & 31;
    const float* base = A + ((size_t)b * NF_ + (size_t)I * 8) * NF_;

    float gmine = gamma_g[b * N_ + t];
    float gI    = __ldg(&gamma_g[b * N_ + I]);

    float4 a0 = make_float4(0.f, 0.f, 0.f, 0.f);
    float4 a1 = make_float4(0.f, 0.f, 0.f, 0.f);
#pragma unroll
    for (int r = 0; r < 8; ++r) {
        const float4* row = reinterpret_cast<const float4*>(base + (size_t)r * NF_);
        float4 f0 = __ldcs(row + t);
        float4 f1 = __ldcs(row + t + 256);
        a0.x += f0.x; a0.y += f0.y; a0.z += f0.z; a0.w += f0.w;
        a1.x += f1.x; a1.y += f1.y; a1.z += f1.z; a1.w += f1.w;
    }
    float s0 = (a0.x + a0.y) + (a0.z + a0.w);
    float s1 = (a1.x + a1.y) + (a1.z + a1.w);
    s0 += __shfl_xor_sync(0xffffffffu, s0, 1);
    s1 += __shfl_xor_sync(0xffffffffu, s1, 1);

    __shared__ float srow[256];
    __shared__ float rA[9], rB[9], rC[9], rD[9];
    if ((t & 1) == 0) {
        srow[(t >> 1)]       = s0 * (1.0f / 64.0f);
        srow[128 + (t >> 1)] = s1 * (1.0f / 64.0f);
    }
    __syncthreads();

    float w = fmaxf(srow[t], 0.0f);                 // relu(A_lat[I, t])

    // ---- round 1: (sum w, max gamma) ----
    {
        float sv = w, mv = gmine;
#pragma unroll
        for (int o = 16; o; o >>= 1) {
            sv += __shfl_xor_sync(0xffffffffu, sv, o);
            mv  = fmaxf(mv, __shfl_xor_sync(0xffffffffu, mv, o));
        }
        if (lane == 0) { rA[wd] = sv; rB[wd] = mv; }
    }
    __syncthreads();
    if (t < 32) {
        float s = (t < 8) ? rA[t] : 0.f;
        float m = (t < 8) ? rB[t] : -3.4e38f;
#pragma unroll
        for (int o = 4; o; o >>= 1) {
            s += __shfl_xor_sync(0xffffffffu, s, o);
            m  = fmaxf(m, __shfl_xor_sync(0xffffffffu, m, o));
        }
        if (t == 0) { rA[8] = s; rB[8] = m; }
    }
    __syncthreads();
    const float rowsum = rA[8], gmax = rB[8];

    float W = (rowsum > EPSF) ? (w / (rowsum + EPSF)) : (1.0f / N_);
    float x  = W + EPSF;
    float x2 = x * x, x4 = x2 * x2, x8 = x4 * x4;
    __nv_bfloat16 kb = __float2bfloat16(x8 * x2);   // K = x^10 (bf16)
    g_K[((size_t)b * N_ + I) * N_ + t] = kb;

    float kf = __bfloat162float(kb);
    float e  = expf(gmine - gmax);

    // ---- round 2: (sum K, sum exp) ----
    {
        float sv = kf, ev = e;
#pragma unroll
        for (int o = 16; o; o >>= 1) {
            sv += __shfl_xor_sync(0xffffffffu, sv, o);
            ev += __shfl_xor_sync(0xffffffffu, ev, o);
        }
        if (lane == 0) { rC[wd] = sv; rD[wd] = ev; }
    }
    __syncthreads();
    if (t < 32) {
        float s = (t < 8) ? rC[t] : 0.f;
        float v = (t < 8) ? rD[t] : 0.f;
#pragma unroll
        for (int o = 4; o; o >>= 1) {
            s += __shfl_xor_sync(0xffffffffu, s, o);
            v += __shfl_xor_sync(0xffffffffu, v, o);
        }
        if (t == 0) { rC[8] = s; rD[8] = v; }
    }
    __syncthreads();
    const float rsK = rC[8], esum = rD[8];

    float pI  = expf(gI - gmax) / esum;
    float u1I = pI / (rsK * (1.0f / N_) + EPSF);    // Kv0 = rsK/256

    atomicAdd(&g_KTu[b * N_ + t], kf * u1I);        // K^T u1, row I's contribution
    if (t == 0) {
        g_p [b * N_ + I] = pI;
        g_u1[b * N_ + I] = u1I;
    }
}

// ---------------------------------------------------------------------------
// Kernel 2: single post-pool K pass + in-kernel finalization via election.
// Grid (16,8) = 128 CTAs, 256 thr. Each chunk: v1, Kv1, u2, conv-check,
// coupling; ONE atomicAdd of the CTA's S partial; 16th arriver per batch
// writes the batch's output (or runs the faithful fallback).
// ---------------------------------------------------------------------------
__global__ void __launch_bounds__(256) epi_main(
    const float* __restrict__ theta_g, const float* __restrict__ gamma_g,
    const float* __restrict__ omega_g, const float* __restrict__ alpha_g,
    const float* __restrict__ logk_g,  float* __restrict__ out)
{
    __shared__ float v1sh[256];     // fallback reuses as v
    __shared__ float tsh[256];
    __shared__ float p_s[256];      // fallback only
    __shared__ float u_s[256];      // fallback only
    __shared__ float kv_s[256];     // fallback only
    __shared__ float spart[16];
    __shared__ float red[10];
    __shared__ int   rank;

    const int b     = blockIdx.y;
    const int chunk = blockIdx.x;
    const int t     = threadIdx.x;
    const int row   = t >> 4;
    const int sub   = t & 15;
    const int i     = chunk * 16 + row;
    const int gi    = b * N_ + i;
    const int j0    = sub * 16;

    float kt = g_KTu[b * N_ + t];
    v1sh[t]  = (1.0f / N_) / (kt + EPSF);
    tsh[t]   = theta_g[b * N_ + t];
    __syncthreads();

    // ---- chunk work: Kv1 + coupling for 16 rows ----
    {
        uint4 k0 = reinterpret_cast<const uint4*>(g_K + (size_t)gi * N_ + j0)[0];
        uint4 k1 = reinterpret_cast<const uint4*>(g_K + (size_t)gi * N_ + j0)[1];
        float kf[16];
        unpack8(k0, kf);
        unpack8(k1, kf + 8);

        const float4* a4 = reinterpret_cast<const float4*>(alpha_g + (size_t)i * N_ + j0);
        float4 al0 = __ldg(a4 + 0);
        float4 al1 = __ldg(a4 + 1);
        float4 al2 = __ldg(a4 + 2);
        float4 al3 = __ldg(a4 + 3);
        float al[16] = {al0.x, al0.y, al0.z, al0.w, al1.x, al1.y, al1.z, al1.w,
                        al2.x, al2.y, al2.z, al2.w, al3.x, al3.y, al3.z, al3.w};

        const float ti = tsh[i];
        float kv = 0.f, cp = 0.f;
#pragma unroll
        for (int x = 0; x < 16; ++x) {
            float kvj = kf[x] * v1sh[j0 + x];
            kv += kvj;
            float d = tsh[j0 + x] - ti - al[x];
            cp = fmaf(kvj, __sinf(d), cp);
        }
#pragma unroll
        for (int o = 8; o; o >>= 1) {
            kv += __shfl_xor_sync(0xffffffffu, kv, o);
            cp += __shfl_xor_sync(0xffffffffu, cp, o);
        }

        if (sub == 0) {
            float u1 = g_u1[gi];
            float u2 = g_p[gi] / (kv + EPSF);
            if (u2 != u1) g_conv[b] = 1;          // not converged after iter 2
            g_u2[gi] = u2;
            g_cp[gi] = cp;
            spart[row] = u2 * kv;                 // S partial (shared, no atomic)
        }
    }
    __syncthreads();

    // ---- one atomicAdd per CTA for S, then election ----
    if (t == 0) {
        float s = 0.f;
#pragma unroll
        for (int r = 0; r < 16; ++r) s += spart[r];
        atomicAdd(&g_S[b], s);
        __threadfence();                           // release CTA's writes
        rank = atomicAdd(&g_cnt[b], 1);
    }
    __syncthreads();
    if (rank != 15) return;

    if (t == 0) __threadfence();                   // acquire peers' writes
    __syncthreads();

    const int conv = __ldcg(&g_conv[b]);

    if (conv == 0) {
        // -------- converged fast path: write the 256 outputs --------
        float S = __ldcg(&g_S[b]);
        float Sinv = 1.0f / (S + EPSF);
        // vectorized u2 / cp reload (64 threads x float4 each)
        float u2, cp;
        {
            __shared__ float4 u4s[64], c4s[64];
            if (t < 64) {
                u4s[t] = __ldcg(reinterpret_cast<const float4*>(g_u2 + b * N_) + t);
                c4s[t] = __ldcg(reinterpret_cast<const float4*>(g_cp + b * N_) + t);
            }
            __syncthreads();
            const float* uf = reinterpret_cast<const float*>(u4s);
            const float* cf = reinterpret_cast<const float*>(c4s);
            u2 = uf[t];
            cp = cf[t];
        }
        float ti = tsh[t];
        float kap = log1pf(expf(logk_g[t]));                 // softplus
        float td  = omega_g[t] + u2 * Sinv * cp + kap * (gamma_g[b * N_ + t] - ti);
        out[b * N_ + t] = ti + td;                           // DT=1, K_COUP=1
    } else {
        // -------- fallback: faithful 10-iter Sinkhorn from scratch --------
        const int wd = t >> 5, lane = t & 31;
        p_s[t] = __ldcg(&g_p[b * N_ + t]);
        u_s[t] = 1.0f / N_;
        v1sh[t] = 1.0f / N_;
        __syncthreads();

        for (int it = 0; it < 10; ++it) {
            // u-update: 8 warps x 32 rows, K from L2
#pragma unroll 1
            for (int k = 0; k < 32; ++k) {
                int ii = wd * 32 + k;
                uint4 kr = reinterpret_cast<const uint4*>(g_K + ((size_t)b * N_ + ii) * N_)[lane];
                float acc = dot8(kr, &v1sh[lane * 8]);
#pragma unroll
                for (int o = 16; o; o >>= 1) acc += __shfl_xor_sync(0xffffffffu, acc, o);
                if (lane == 0) u_s[ii] = p_s[ii] / (acc + EPSF);
            }
            __syncthreads();
            // v-update: thread t = column j
            float s = 0.f;
#pragma unroll 1
            for (int ii = 0; ii < N_; ++ii)
                s = fmaf(__bfloat162float(g_K[((size_t)b * N_ + ii) * N_ + t]), u_s[ii], s);
            __syncthreads();
            v1sh[t] = (1.0f / N_) / (s + EPSF);
            __syncthreads();
        }

        // final Kv, S
#pragma unroll 1
        for (int k = 0; k < 32; ++k) {
            int ii = wd * 32 + k;
            uint4 kr = reinterpret_cast<const uint4*>(g_K + ((size_t)b * N_ + ii) * N_)[lane];
            float acc = dot8(kr, &v1sh[lane * 8]);
#pragma unroll
            for (int o = 16; o; o >>= 1) acc += __shfl_xor_sync(0xffffffffu, acc, o);
            if (lane == 0) kv_s[ii] = acc;
        }
        __syncthreads();
        float S = blk_sum256(u_s[t] * kv_s[t], red);
        float Sinv = 1.0f / (S + EPSF);

        // coupling: thread t = row i
        float ti = tsh[t];
        float acc = 0.f;
#pragma unroll 1
        for (int j = 0; j < N_; ++j) {
            float kv = __bfloat162float(g_K[((size_t)b * N_ + t) * N_ + j]) * v1sh[j];
            float d  = tsh[j] - ti - alpha_g[(size_t)t * N_ + j];
            acc = fmaf(kv, __sinf(d), acc);
        }
        float kap = log1pf(expf(logk_g[t]));
        float td  = omega_g[t] + u_s[t] * Sinv * acc + kap * (gamma_g[b * N_ + t] - ti);
        out[b * N_ + t] = ti + td;
    }

    // -------- housekeeping for next graph replay --------
    g_KTu[b * N_ + t] = 0.f;
    if (t == 0) { g_S[b] = 0.f; g_conv[b] = 0; g_cnt[b] = 0; }
}

// ---------------------------------------------------------------------------
extern "C" void kernel_launch(void* const* d_in, const int* in_sizes, int n_in,
                              void* d_out, int out_size)
{
    const float* theta = (const float*)d_in[0];
    const float* gamma = (const float*)d_in[1];
    const float* A     = (const float*)d_in[2];
    const float* omega = (const float*)d_in[3];
    const float* alpha = (const float*)d_in[4];
    const float* logk  = (const float*)d_in[5];
    float* out = (float*)d_out;

    dim3 g1(256, 8);
    pool_build_k<<<g1, 256>>>(A, gamma);

    dim3 g2(16, 8);
    epi_main<<<g2, 256>>>(theta, gamma, omega, alpha, logk, out);
}

// round 8
// speedup vs baseline: 1.0656x; 1.0072x over previous
#include <cuda_runtime.h>
#include <cuda_bf16.h>
#include <cstdint>

#define EPSF 1e-8f
static constexpr int B_  = 8;
static constexpr int N_  = 256;
static constexpr int NF_ = 2048;

__device__ __nv_bfloat16 g_K[B_ * N_ * N_];   // bf16 K, L2-resident
__device__ float g_KTu[B_ * N_];              // accumulated K^T u1 (reset by kfinal)
__device__ float g_p  [B_ * N_];
__device__ float g_u1 [B_ * N_];
__device__ float g_u2 [B_ * N_];
__device__ float g_cp [B_ * N_];              // coupling accumulator per row
__device__ float g_S  [B_];
__device__ int   g_conv[B_];

// ---------------------------------------------------------------------------
// helpers
// ---------------------------------------------------------------------------
__device__ __forceinline__ void unpack8(uint4 kr, float* f)
{
    float2 f0 = __bfloat1622float2(*reinterpret_cast<__nv_bfloat162*>(&kr.x));
    float2 f1 = __bfloat1622float2(*reinterpret_cast<__nv_bfloat162*>(&kr.y));
    float2 f2 = __bfloat1622float2(*reinterpret_cast<__nv_bfloat162*>(&kr.z));
    float2 f3 = __bfloat1622float2(*reinterpret_cast<__nv_bfloat162*>(&kr.w));
    f[0] = f0.x; f[1] = f0.y; f[2] = f1.x; f[3] = f1.y;
    f[4] = f2.x; f[5] = f2.y; f[6] = f3.x; f[7] = f3.y;
}

__device__ __forceinline__ float dot8(uint4 kr, const float* vj)
{
    float kf[8];
    unpack8(kr, kf);
    float acc = 0.f;
#pragma unroll
    for (int x = 0; x < 8; ++x) acc = fmaf(kf[x], vj[x], acc);
    return acc;
}

// 256-thread broadcast sum (fallback path)
__device__ __forceinline__ float blk_sum256(float val, float* red)
{
#pragma unroll
    for (int o = 16; o; o >>= 1) val += __shfl_xor_sync(0xffffffffu, val, o);
    if ((threadIdx.x & 31) == 0) red[threadIdx.x >> 5] = val;
    __syncthreads();
    if (threadIdx.x < 32) {
        float s = (threadIdx.x < 8) ? red[threadIdx.x] : 0.f;
#pragma unroll
        for (int o = 4; o; o >>= 1) s += __shfl_xor_sync(0xffffffffu, s, o);
        if (threadIdx.x == 0) red[8] = s;
    }
    __syncthreads();
    float r = red[8];
    __syncthreads();
    return r;
}

// ---------------------------------------------------------------------------
// Kernel 1: pooling -> K (bf16); combined reductions; u1; REDG K^T u1.
// Also prefetches this CTA's 128B slice of alpha into L2 for kernel 2.
// Grid (256,8), 256 threads, <=32 regs (8 CTAs/SM).
// ---------------------------------------------------------------------------
__global__ void __launch_bounds__(256, 8) pool_build_k(
    const float* __restrict__ A, const float* __restrict__ gamma_g,
    const float* __restrict__ alpha_g)
{
    const int I = blockIdx.x, b = blockIdx.y;
    const int t = threadIdx.x;
    const int wd = t >> 5, lane = t & 31;
    const float* base = A + ((size_t)b * NF_ + (size_t)I * 8) * NF_;

    // warm L2 with alpha (each CTA covers 32 floats = 128 B; 2048 CTAs = 256 KB)
    if (t == 0) {
        const float* ap = alpha_g + ((size_t)b * N_ + I) * 32;
        asm volatile("prefetch.global.L2 [%0];" :: "l"(ap));
    }

    float gmine = gamma_g[b * N_ + t];
    float gI    = __ldg(&gamma_g[b * N_ + I]);

    float4 a0 = make_float4(0.f, 0.f, 0.f, 0.f);
    float4 a1 = make_float4(0.f, 0.f, 0.f, 0.f);
#pragma unroll
    for (int r = 0; r < 8; ++r) {
        const float4* row = reinterpret_cast<const float4*>(base + (size_t)r * NF_);
        float4 f0 = __ldcs(row + t);
        float4 f1 = __ldcs(row + t + 256);
        a0.x += f0.x; a0.y += f0.y; a0.z += f0.z; a0.w += f0.w;
        a1.x += f1.x; a1.y += f1.y; a1.z += f1.z; a1.w += f1.w;
    }
    float s0 = (a0.x + a0.y) + (a0.z + a0.w);
    float s1 = (a1.x + a1.y) + (a1.z + a1.w);
    s0 += __shfl_xor_sync(0xffffffffu, s0, 1);
    s1 += __shfl_xor_sync(0xffffffffu, s1, 1);

    __shared__ float srow[256];
    __shared__ float rA[9], rB[9], rC[9], rD[9];
    if ((t & 1) == 0) {
        srow[(t >> 1)]       = s0 * (1.0f / 64.0f);
        srow[128 + (t >> 1)] = s1 * (1.0f / 64.0f);
    }
    __syncthreads();

    float w = fmaxf(srow[t], 0.0f);                 // relu(A_lat[I, t])

    // ---- round 1: (sum w, max gamma) ----
    {
        float sv = w, mv = gmine;
#pragma unroll
        for (int o = 16; o; o >>= 1) {
            sv += __shfl_xor_sync(0xffffffffu, sv, o);
            mv  = fmaxf(mv, __shfl_xor_sync(0xffffffffu, mv, o));
        }
        if (lane == 0) { rA[wd] = sv; rB[wd] = mv; }
    }
    __syncthreads();
    if (t < 32) {
        float s = (t < 8) ? rA[t] : 0.f;
        float m = (t < 8) ? rB[t] : -3.4e38f;
#pragma unroll
        for (int o = 4; o; o >>= 1) {
            s += __shfl_xor_sync(0xffffffffu, s, o);
            m  = fmaxf(m, __shfl_xor_sync(0xffffffffu, m, o));
        }
        if (t == 0) { rA[8] = s; rB[8] = m; }
    }
    __syncthreads();
    const float rowsum = rA[8], gmax = rB[8];

    float W = (rowsum > EPSF) ? (w / (rowsum + EPSF)) : (1.0f / N_);
    float x  = W + EPSF;
    float x2 = x * x, x4 = x2 * x2, x8 = x4 * x4;
    __nv_bfloat16 kb = __float2bfloat16(x8 * x2);   // K = x^10 (bf16)
    g_K[((size_t)b * N_ + I) * N_ + t] = kb;

    float kf = __bfloat162float(kb);
    float e  = expf(gmine - gmax);

    // ---- round 2: (sum K, sum exp) ----
    {
        float sv = kf, ev = e;
#pragma unroll
        for (int o = 16; o; o >>= 1) {
            sv += __shfl_xor_sync(0xffffffffu, sv, o);
            ev += __shfl_xor_sync(0xffffffffu, ev, o);
        }
        if (lane == 0) { rC[wd] = sv; rD[wd] = ev; }
    }
    __syncthreads();
    if (t < 32) {
        float s = (t < 8) ? rC[t] : 0.f;
        float v = (t < 8) ? rD[t] : 0.f;
#pragma unroll
        for (int o = 4; o; o >>= 1) {
            s += __shfl_xor_sync(0xffffffffu, s, o);
            v += __shfl_xor_sync(0xffffffffu, v, o);
        }
        if (t == 0) { rC[8] = s; rD[8] = v; }
    }
    __syncthreads();
    const float rsK = rC[8], esum = rD[8];

    float pI  = expf(gI - gmax) / esum;
    float u1I = pI / (rsK * (1.0f / N_) + EPSF);    // Kv0 = rsK/256

    atomicAdd(&g_KTu[b * N_ + t], kf * u1I);        // K^T u1, row I's contribution
    if (t == 0) {
        g_p [b * N_ + I] = pI;
        g_u1[b * N_ + I] = u1I;
    }
}

// ---------------------------------------------------------------------------
// Kernel 2: single post-pool K pass. Grid (32,8) = 256 CTAs, 256 thr.
// One warp per row (8 rows/CTA): v1, Kv1, u2, conv-check, coupling;
// one atomicAdd per CTA for the S partial. No election.
// ---------------------------------------------------------------------------
__global__ void __launch_bounds__(256) epi_main(
    const float* __restrict__ theta_g, const float* __restrict__ alpha_g)
{
    __shared__ float v1sh[256];
    __shared__ float tsh[256];
    __shared__ float spart[8];

    const int b     = blockIdx.y;
    const int chunk = blockIdx.x;          // 0..31
    const int t     = threadIdx.x;
    const int row   = t >> 5;              // 0..7
    const int lane  = t & 31;
    const int i     = chunk * 8 + row;     // output row
    const int gi    = b * N_ + i;
    const int j0    = lane * 8;

    float kt = g_KTu[b * N_ + t];
    v1sh[t]  = (1.0f / N_) / (kt + EPSF);
    tsh[t]   = theta_g[b * N_ + t];
    __syncthreads();

    // ---- one warp per row: Kv1 + coupling over 256 cols (8 per lane) ----
    uint4 kr = *reinterpret_cast<const uint4*>(g_K + (size_t)gi * N_ + j0);
    float kf[8];
    unpack8(kr, kf);

    const float4* a4 = reinterpret_cast<const float4*>(alpha_g + (size_t)i * N_ + j0);
    float4 al0 = __ldg(a4 + 0);
    float4 al1 = __ldg(a4 + 1);
    float al[8] = {al0.x, al0.y, al0.z, al0.w, al1.x, al1.y, al1.z, al1.w};

    const float ti = tsh[i];
    float kv = 0.f, cp = 0.f;
#pragma unroll
    for (int x = 0; x < 8; ++x) {
        float kvj = kf[x] * v1sh[j0 + x];
        kv += kvj;
        float d = tsh[j0 + x] - ti - al[x];
        cp = fmaf(kvj, __sinf(d), cp);
    }
#pragma unroll
    for (int o = 16; o; o >>= 1) {
        kv += __shfl_xor_sync(0xffffffffu, kv, o);
        cp += __shfl_xor_sync(0xffffffffu, cp, o);
    }

    if (lane == 0) {
        float u1 = g_u1[gi];
        float u2 = g_p[gi] / (kv + EPSF);
        if (u2 != u1) g_conv[b] = 1;       // not converged after iter 2
        g_u2[gi] = u2;
        g_cp[gi] = cp;
        spart[row] = u2 * kv;
    }
    __syncthreads();

    if (t == 0) {
        float s = 0.f;
#pragma unroll
        for (int r = 0; r < 8; ++r) s += spart[r];
        atomicAdd(&g_S[b], s);             // one atomic per CTA
    }
}

// ---------------------------------------------------------------------------
// Kernel 3: final output (converged path is pointwise) + housekeeping.
// Grid 8, 256 threads. Fallback: faithful 10-iter Sinkhorn (never taken
// for this data, correct for arbitrary data).
// ---------------------------------------------------------------------------
__global__ void __launch_bounds__(256) kfinal(
    const float* __restrict__ theta_g, const float* __restrict__ gamma_g,
    const float* __restrict__ omega_g, const float* __restrict__ alpha_g,
    const float* __restrict__ logk_g,  float* __restrict__ out)
{
    __shared__ float red[10];
    __shared__ float vsh[256], tsh[256], p_s[256], u_s[256], kv_s[256];

    const int b = blockIdx.x;
    const int t = threadIdx.x;
    const int conv = g_conv[b];

    if (conv == 0) {
        // -------- converged fast path --------
        float S    = g_S[b];
        float Sinv = 1.0f / (S + EPSF);
        float u2   = g_u2[b * N_ + t];
        float cp   = g_cp[b * N_ + t];
        float ti   = theta_g[b * N_ + t];
        float kap  = log1pf(expf(logk_g[t]));               // softplus
        float td   = omega_g[t] + u2 * Sinv * cp + kap * (gamma_g[b * N_ + t] - ti);
        out[b * N_ + t] = ti + td;                          // DT=1, K_COUP=1
    } else {
        // -------- fallback: faithful 10-iter Sinkhorn from scratch --------
        const int wd = t >> 5, lane = t & 31;
        p_s[t] = g_p[b * N_ + t];
        u_s[t] = 1.0f / N_;
        vsh[t] = 1.0f / N_;
        tsh[t] = theta_g[b * N_ + t];
        __syncthreads();

        for (int it = 0; it < 10; ++it) {
            // u-update: 8 warps x 32 rows, K from L2
#pragma unroll 1
            for (int k = 0; k < 32; ++k) {
                int ii = wd * 32 + k;
                uint4 kr = reinterpret_cast<const uint4*>(g_K + ((size_t)b * N_ + ii) * N_)[lane];
                float acc = dot8(kr, &vsh[lane * 8]);
#pragma unroll
                for (int o = 16; o; o >>= 1) acc += __shfl_xor_sync(0xffffffffu, acc, o);
                if (lane == 0) u_s[ii] = p_s[ii] / (acc + EPSF);
            }
            __syncthreads();
            // v-update: thread t = column j
            float s = 0.f;
#pragma unroll 1
            for (int ii = 0; ii < N_; ++ii)
                s = fmaf(__bfloat162float(g_K[((size_t)b * N_ + ii) * N_ + t]), u_s[ii], s);
            __syncthreads();
            vsh[t] = (1.0f / N_) / (s + EPSF);
            __syncthreads();
        }

        // final Kv, S
#pragma unroll 1
        for (int k = 0; k < 32; ++k) {
            int ii = wd * 32 + k;
            uint4 kr = reinterpret_cast<const uint4*>(g_K + ((size_t)b * N_ + ii) * N_)[lane];
            float acc = dot8(kr, &vsh[lane * 8]);
#pragma unroll
            for (int o = 16; o; o >>= 1) acc += __shfl_xor_sync(0xffffffffu, acc, o);
            if (lane == 0) kv_s[ii] = acc;
        }
        __syncthreads();
        float S = blk_sum256(u_s[t] * kv_s[t], red);
        float Sinv = 1.0f / (S + EPSF);

        // coupling: thread t = row i
        float ti = tsh[t];
        float acc = 0.f;
#pragma unroll 1
        for (int j = 0; j < N_; ++j) {
            float kv = __bfloat162float(g_K[((size_t)b * N_ + t) * N_ + j]) * vsh[j];
            float d  = tsh[j] - ti - alpha_g[(size_t)t * N_ + j];
            acc = fmaf(kv, __sinf(d), acc);
        }
        float kap = log1pf(expf(logk_g[t]));
        float td  = omega_g[t] + u_s[t] * Sinv * acc + kap * (gamma_g[b * N_ + t] - ti);
        out[b * N_ + t] = ti + td;
    }

    // -------- housekeeping for next graph replay --------
    __syncthreads();
    g_KTu[b * N_ + t] = 0.f;
    if (t == 0) { g_S[b] = 0.f; g_conv[b] = 0; }
}

// ---------------------------------------------------------------------------
extern "C" void kernel_launch(void* const* d_in, const int* in_sizes, int n_in,
                              void* d_out, int out_size)
{
    const float* theta = (const float*)d_in[0];
    const float* gamma = (const float*)d_in[1];
    const float* A     = (const float*)d_in[2];
    const float* omega = (const float*)d_in[3];
    const float* alpha = (const float*)d_in[4];
    const float* logk  = (const float*)d_in[5];
    float* out = (float*)d_out;

    dim3 g1(256, 8);
    pool_build_k<<<g1, 256>>>(A, gamma, alpha);

    dim3 g2(32, 8);
    epi_main<<<g2, 256>>>(theta, alpha);

    kfinal<<<B_, 256>>>(theta, gamma, omega, alpha, logk, out);
}